// round 2
// baseline (speedup 1.0000x reference)
#include <cuda_runtime.h>

#define NN 1024
#define BB 128
#define TS 32
#define NT (NN/TS)   // 32 tile rows/cols

// Partial results per (tile, batch). Zero-initialized at module load; inactive
// (lower-triangular) tiles rewrite zeros every launch so content is always
// deterministic regardless of prior launches.
__device__ float g_qpart[NT*NT][BB];

__global__ __launch_bounds__(128, 5)
void potts_tile_kernel(const float* __restrict__ vec,
                       const float* __restrict__ W)
{
    const int ti = blockIdx.y, tj = blockIdx.x;
    const int lin = ti * NT + tj;
    const int tid = threadIdx.x;

    if (tj < ti) {            // lower-triangular tile: contribute exactly zero
        g_qpart[lin][tid] = 0.0f;
        return;
    }

    __shared__ float Wt[TS][TS + 1];   // padded: conflict-free row reads
    __shared__ float Vi[BB][TS + 1];   // padded: lane==b reads conflict-free
    __shared__ float Vj[BB][TS + 1];
    __shared__ float rs[TS];           // masked row sums of tile
    __shared__ float cs[TS];           // masked col sums of tile
    __shared__ float sT0;              // masked tile sum

    const int i0 = ti * TS, j0 = tj * TS;
    const bool diag = (ti == tj);

    // ---- stage W tile (apply triu mask on the diagonal tile) ----
    #pragma unroll
    for (int idx = tid; idx < TS * TS; idx += 128) {
        int r = idx >> 5, c = idx & 31;
        float w = W[(i0 + r) * NN + j0 + c];
        if (diag && c < r) w = 0.0f;
        Wt[r][c] = w;
    }
    // ---- stage vector tiles for all 128 batches (coalesced) ----
    for (int idx = tid; idx < BB * TS; idx += 128) {
        int b = idx >> 5, c = idx & 31;
        Vi[b][c] = vec[b * NN + i0 + c];
        Vj[b][c] = vec[b * NN + j0 + c];
    }
    __syncthreads();

    // ---- batch-independent tile reductions ----
    if (tid < TS) {
        float s = 0.0f;
        #pragma unroll
        for (int j = 0; j < TS; j++) s += Wt[tid][j];
        rs[tid] = s;
    } else if (tid < 2 * TS) {
        int j = tid - TS;
        float s = 0.0f;
        #pragma unroll
        for (int i = 0; i < TS; i++) s += Wt[i][j];
        cs[j] = s;
    }
    __syncthreads();
    if (tid == 0) {
        float s = 0.0f;
        #pragma unroll
        for (int i = 0; i < TS; i++) s += rs[i];
        sT0 = s;
    }
    __syncthreads();

    // ---- per-batch: one thread per batch b ----
    const int b = tid;
    float vjr[TS];
    #pragma unroll
    for (int j = 0; j < TS; j++) vjr[j] = Vj[b][j];

    float lj = 0.0f;
    #pragma unroll
    for (int j = 0; j < TS; j++) lj += cs[j] * vjr[j];

    float q = 0.0f, li = 0.0f;
    #pragma unroll 4
    for (int i = 0; i < TS; i++) {
        float inner = 0.0f;
        #pragma unroll
        for (int j = 0; j < TS; j++) inner += Wt[i][j] * vjr[j];
        float vi = Vi[b][i];
        q  += vi * inner;    // bilinear term
        li += vi * rs[i];    // linear (row) term
    }

    // tile contribution: sum_{tile,masked} W * (1 - vi - vj + 2 vi vj)
    g_qpart[lin][b] = sT0 - li - lj + 2.0f * q;
}

__global__ __launch_bounds__(256)
void potts_reduce_kernel(float* __restrict__ out)
{
    const int b = blockIdx.x;
    const int tid = threadIdx.x;
    float s = 0.0f;
    #pragma unroll
    for (int lin = tid; lin < NT * NT; lin += 256)
        s += g_qpart[lin][b];

    __shared__ float sh[256];
    sh[tid] = s;
    __syncthreads();
    #pragma unroll
    for (int st = 128; st > 0; st >>= 1) {
        if (tid < st) sh[tid] += sh[tid + st];
        __syncthreads();
    }
    if (tid == 0) out[b] = sh[0];
}

extern "C" void kernel_launch(void* const* d_in, const int* in_sizes, int n_in,
                              void* d_out, int out_size)
{
    const float* vec = (const float*)d_in[0];   // vector   [128, 1024]
    const float* W   = (const float*)d_in[1];   // interactions [1024, 1024]
    float* out = (float*)d_out;                 // [128]

    dim3 grid(NT, NT);
    potts_tile_kernel<<<grid, 128>>>(vec, W);
    potts_reduce_kernel<<<BB, 256>>>(out);
}